// round 3
// baseline (speedup 1.0000x reference)
#include <cuda_runtime.h>
#include <cstdint>

#define T_STEPS 512
#define BATCH   64
#define DIN     1024
#define HID     1024
#define N3      3072   // [z | r | c] precomputed x-projections

// ---------------- static device scratch (no runtime allocation) ----------------
__device__ float g_P[(size_t)T_STEPS * BATCH * N3];   // 384 MB: x-projections
__device__ float g_WtP[DIN * N3];                     // k-major weights for phase 1
__device__ float g_WtA[HID * 2048];                   // WtA[k][j] = Wfc[j][1024+k]
__device__ float g_WtB[HID * HID];                    // WtB[k][j] = Wfc2[j][1024+k]
__device__ float g_hT[HID * BATCH];                   // h transposed [k][b]
__device__ float g_hb[BATCH * HID];                   // h row-major [b][k]
__device__ float g_PA[16 * BATCH * 2048];             // split-K partials stage A
__device__ float g_PB[32 * BATCH * HID];              // split-K partials stage B
__device__ volatile unsigned g_bar;                   // grid barrier counter

// ---------------- init ----------------
__global__ void init_kernel() {
    int i = blockIdx.x * blockDim.x + threadIdx.x;
    if (i == 0) g_bar = 0u;
    if (i < HID * BATCH) { g_hT[i] = 1e-9f; g_hb[i] = 1e-9f; }
}

// ---------------- repack weights to k-major ----------------
__global__ void repack_kernel(const float* __restrict__ Wfc,
                              const float* __restrict__ Wfc2) {
    int i = blockIdx.x * blockDim.x + threadIdx.x;
    const int szP = DIN * N3;            // 3,145,728
    const int szA = HID * 2048;          // 2,097,152
    const int szB = HID * HID;           // 1,048,576
    if (i < szP) {
        int k = i / N3, n = i % N3;
        g_WtP[i] = (n < 2048) ? Wfc[(size_t)n * 2048 + k]
                              : Wfc2[(size_t)(n - 2048) * 2048 + k];
    } else if (i < szP + szA) {
        int j2 = i - szP; int k = j2 >> 11, j = j2 & 2047;
        g_WtA[j2] = Wfc[(size_t)j * 2048 + 1024 + k];
    } else if (i < szP + szA + szB) {
        int j2 = i - szP - szA; int k = j2 >> 10, j = j2 & 1023;
        g_WtB[j2] = Wfc2[(size_t)j * 2048 + 1024 + k];
    }
}

// ---------------- phase 1: P = X (32768x1024) @ WtP (1024x3072) ----------------
__global__ void __launch_bounds__(256) gemm_p_kernel(const float* __restrict__ X) {
    __shared__ float As[8][132];   // padded transpose-store
    __shared__ float Bs[8][128];
    const int tid = threadIdx.x;
    const int n0 = blockIdx.x << 7, m0 = blockIdx.y << 7;
    const int tx8 = (tid & 15) << 3, ty8 = (tid >> 4) << 3;
    const int ar = tid >> 1, ah = (tid & 1) << 2;
    const int br = tid >> 5, bc = (tid & 31) << 2;
    float acc[8][8];
#pragma unroll
    for (int i = 0; i < 8; i++)
#pragma unroll
        for (int j = 0; j < 8; j++) acc[i][j] = 0.f;

    for (int k0 = 0; k0 < DIN; k0 += 8) {
        float4 av = *(const float4*)(X + (size_t)(m0 + ar) * DIN + k0 + ah);
        As[ah + 0][ar] = av.x; As[ah + 1][ar] = av.y;
        As[ah + 2][ar] = av.z; As[ah + 3][ar] = av.w;
        *(float4*)&Bs[br][bc] =
            *(const float4*)(g_WtP + (size_t)(k0 + br) * N3 + n0 + bc);
        __syncthreads();
#pragma unroll
        for (int k = 0; k < 8; k++) {
            float4 a0 = *(const float4*)&As[k][ty8];
            float4 a1 = *(const float4*)&As[k][ty8 + 4];
            float4 b0 = *(const float4*)&Bs[k][tx8];
            float4 b1 = *(const float4*)&Bs[k][tx8 + 4];
            float a[8] = {a0.x, a0.y, a0.z, a0.w, a1.x, a1.y, a1.z, a1.w};
            float b[8] = {b0.x, b0.y, b0.z, b0.w, b1.x, b1.y, b1.z, b1.w};
#pragma unroll
            for (int i = 0; i < 8; i++)
#pragma unroll
                for (int j = 0; j < 8; j++)
                    acc[i][j] = fmaf(a[i], b[j], acc[i][j]);
        }
        __syncthreads();
    }
#pragma unroll
    for (int i = 0; i < 8; i++) {
        float* cp = g_P + (size_t)(m0 + ty8 + i) * N3 + n0 + tx8;
        *(float4*)cp       = make_float4(acc[i][0], acc[i][1], acc[i][2], acc[i][3]);
        *(float4*)(cp + 4) = make_float4(acc[i][4], acc[i][5], acc[i][6], acc[i][7]);
    }
}

// ---------------- robust grid barrier (monotonic counter) ----------------
__device__ __forceinline__ void grid_bar(unsigned target) {
    __threadfence();          // every thread: flush my stores to L2
    __syncthreads();          // whole block fenced + arrived locally
    if (threadIdx.x == 0) {
        atomicAdd((unsigned*)&g_bar, 1u);
        while (g_bar < target) __nanosleep(64);
        __threadfence();      // acquire: order later loads after the observation
    }
    __syncthreads();
}

// ---------------- persistent sequential kernel ----------------
// grid = #SMs, __launch_bounds__(256,1) => one block per SM, all co-resident.
__global__ void __launch_bounds__(256, 1) seq_kernel(float* __restrict__ out) {
    __shared__ float As[16][64];
    __shared__ float Bs[16][256];
    __shared__ float rhs[32][65];
    const int tid = threadIdx.x, bid = blockIdx.x, nb = gridDim.x;
    const int gtid = bid * 256 + tid, nthr = nb * 256;
    const int tx8 = (tid & 31) << 3;
    const int ty8 = (tid >> 5) << 3;
    unsigned bar_t = 0;

    for (int t = 0; t < T_STEPS; t++) {
        const float* Pt = g_P + (size_t)t * (BATCH * N3);

        // ======== stage A: PA[kc] = hT[kc-slice] @ WtA  (16 kc x 8 ct = 128 units)
        if (bid < 128) {
            const int kc = bid >> 3, ct = bid & 7;
            const float* Ak = g_hT + kc * 64 * 64;
            const float* Bk = g_WtA + (size_t)(kc * 64) * 2048 + ct * 256;
            float* C = g_PA + (size_t)kc * (BATCH * 2048) + ct * 256;
            float acc[8][8];
#pragma unroll
            for (int i = 0; i < 8; i++)
#pragma unroll
                for (int j = 0; j < 8; j++) acc[i][j] = 0.f;

            for (int kb = 0; kb < 64; kb += 16) {
                {
                    int r = tid >> 4, c4 = (tid & 15) << 2;
                    float4 v = __ldcg((const float4*)(Ak + (kb + r) * 64 + c4));
                    *(float4*)&As[r][c4] = v;
                }
#pragma unroll
                for (int i = 0; i < 4; i++) {
                    int idx = (i << 8) | tid;
                    int r = idx >> 6, c4 = (idx & 63) << 2;
                    *(float4*)&Bs[r][c4] =
                        *(const float4*)(Bk + (size_t)(kb + r) * 2048 + c4);
                }
                __syncthreads();
#pragma unroll
                for (int k = 0; k < 16; k++) {
                    float4 a0 = *(const float4*)&As[k][ty8];
                    float4 a1 = *(const float4*)&As[k][ty8 + 4];
                    float4 b0 = *(const float4*)&Bs[k][tx8];
                    float4 b1 = *(const float4*)&Bs[k][tx8 + 4];
                    float a[8] = {a0.x, a0.y, a0.z, a0.w, a1.x, a1.y, a1.z, a1.w};
                    float b[8] = {b0.x, b0.y, b0.z, b0.w, b1.x, b1.y, b1.z, b1.w};
#pragma unroll
                    for (int i = 0; i < 8; i++)
#pragma unroll
                        for (int j = 0; j < 8; j++)
                            acc[i][j] = fmaf(a[i], b[j], acc[i][j]);
                }
                __syncthreads();
            }
#pragma unroll
            for (int i = 0; i < 8; i++) {
                float* cp = C + (size_t)(ty8 + i) * 2048 + tx8;
                *(float4*)cp       = make_float4(acc[i][0], acc[i][1], acc[i][2], acc[i][3]);
                *(float4*)(cp + 4) = make_float4(acc[i][4], acc[i][5], acc[i][6], acc[i][7]);
            }
        }
        bar_t += nb; grid_bar(bar_t);

        // ======== stage B: fused r-reduce + (r*h) @ WtB  (32 kc x 4 ct = 128 units)
        if (bid < 128) {
            const int kc = bid >> 2, ct = bid & 3;

            // prologue: reduce r-half of PA for k in [kc*32, kc*32+32), all batches
            for (int idx = tid; idx < 32 * 64; idx += 256) {
                int kl = idx & 31, b = idx >> 5;
                int k = kc * 32 + kl;
                float s = Pt[b * N3 + 1024 + k];
#pragma unroll
                for (int c = 0; c < 16; c++)
                    s += __ldcg(&g_PA[c * (BATCH * 2048) + b * 2048 + 1024 + k]);
                float r = 1.0f / (1.0f + __expf(-s));
                rhs[kl][b] = r * __ldcg(&g_hb[(b << 10) + k]);
            }
            __syncthreads();

            const float* Bk = g_WtB + (size_t)(kc * 32) * 1024 + ct * 256;
            float* C = g_PB + (size_t)kc * (BATCH * 1024) + ct * 256;
            float acc[8][8];
#pragma unroll
            for (int i = 0; i < 8; i++)
#pragma unroll
                for (int j = 0; j < 8; j++) acc[i][j] = 0.f;

            for (int kb = 0; kb < 32; kb += 16) {
#pragma unroll
                for (int i = 0; i < 4; i++) {
                    int idx = (i << 8) | tid;
                    int r = idx >> 6, c4 = (idx & 63) << 2;
                    *(float4*)&Bs[r][c4] =
                        *(const float4*)(Bk + (size_t)(kb + r) * 1024 + c4);
                }
                __syncthreads();
#pragma unroll
                for (int k = 0; k < 16; k++) {
                    const float* ar = &rhs[kb + k][0];
                    float4 b0 = *(const float4*)&Bs[k][tx8];
                    float4 b1 = *(const float4*)&Bs[k][tx8 + 4];
                    float b[8] = {b0.x, b0.y, b0.z, b0.w, b1.x, b1.y, b1.z, b1.w};
#pragma unroll
                    for (int i = 0; i < 8; i++) {
                        float a = ar[ty8 + i];
#pragma unroll
                        for (int j = 0; j < 8; j++)
                            acc[i][j] = fmaf(a, b[j], acc[i][j]);
                    }
                }
                __syncthreads();
            }
#pragma unroll
            for (int i = 0; i < 8; i++) {
                float* cp = C + (size_t)(ty8 + i) * 1024 + tx8;
                *(float4*)cp       = make_float4(acc[i][0], acc[i][1], acc[i][2], acc[i][3]);
                *(float4*)(cp + 4) = make_float4(acc[i][4], acc[i][5], acc[i][6], acc[i][7]);
            }
        }
        bar_t += nb; grid_bar(bar_t);

        // ======== stage C: z reduce + tanh(c) + blend + h update + output
        float* ot = out + (size_t)t * (BATCH * HID);
        for (int o = gtid; o < BATCH * HID; o += nthr) {
            int b = o >> 10, j = o & 1023;
            float sz = Pt[b * N3 + j];
#pragma unroll
            for (int c = 0; c < 16; c++)
                sz += __ldcg(&g_PA[c * (BATCH * 2048) + b * 2048 + j]);
            float z = 1.0f / (1.0f + __expf(-sz));

            float sc = Pt[b * N3 + 2048 + j];
#pragma unroll
            for (int c = 0; c < 32; c++)
                sc += __ldcg(&g_PB[c * (BATCH * 1024) + o]);
            float cv = tanhf(sc);

            float h = __ldcg(&g_hb[o]);
            float hn = fmaf(z, cv - h, h);   // (1-z)*h + z*c
            ot[o] = hn;
            g_hb[o] = hn;
            g_hT[(j << 6) + b] = hn;
        }
        bar_t += nb; grid_bar(bar_t);
    }
}

// ---------------- launch (4 graph nodes total) ----------------
extern "C" void kernel_launch(void* const* d_in, const int* in_sizes, int n_in,
                              void* d_out, int out_size) {
    const float* x    = (const float*)d_in[0];   // [512, 64, 1024]
    const float* Wfc  = (const float*)d_in[1];   // [2048, 2048]
    const float* Wfc2 = (const float*)d_in[2];   // [1024, 2048]
    // d_in[3] (w_hh), d_in[4] (bias): dead — delta_u never reaches the output
    float* out = (float*)d_out;                  // [512, 64, 1024]

    int sms = 148;
    cudaDeviceGetAttribute(&sms, cudaDevAttrMultiProcessorCount, 0);
    if (sms > 148) sms = 148;   // seq_kernel work mapping assumes >=128, uses min(n,148)

    init_kernel<<<256, 256>>>();
    repack_kernel<<<24576, 256>>>(Wfc, Wfc2);
    {
        dim3 g(N3 / 128, (T_STEPS * BATCH) / 128);  // 24 x 256 tiles
        gemm_p_kernel<<<g, 256>>>(x);
    }
    seq_kernel<<<sms, 256>>>(out);
}

// round 5
// speedup vs baseline: 1.2588x; 1.2588x over previous
#include <cuda_runtime.h>
#include <cuda_bf16.h>
#include <mma.h>
#include <cstdint>

using namespace nvcuda;

#define T_STEPS 512
#define BATCH   64
#define DIN     1024
#define HID     1024
#define N3      3072   // [z | r | c] precomputed x-projections
#define MROWS   (T_STEPS * BATCH)   // 32768

// ---------------- static device scratch (no runtime allocation) ----------------
__device__ float g_P[(size_t)MROWS * N3];               // 384 MB: x-projections (fp32)
__device__ __nv_bfloat16 g_Xh[(size_t)MROWS * DIN];     // X hi (bf16)
__device__ __nv_bfloat16 g_Xl[(size_t)MROWS * DIN];     // X lo
__device__ __nv_bfloat16 g_Bh[(size_t)N3 * DIN];        // W rows [n][k] hi
__device__ __nv_bfloat16 g_Bl[(size_t)N3 * DIN];        // W rows [n][k] lo
__device__ float g_WtA[HID * 2048];                     // WtA[k][j] = Wfc[j][1024+k]
__device__ float g_WtB[HID * HID];                      // WtB[k][j] = Wfc2[j][1024+k]
__device__ float g_hT[HID * BATCH];                     // h transposed [k][b]
__device__ float g_hb[BATCH * HID];                     // h row-major [b][k]
__device__ float g_PA[16 * BATCH * 2048];               // split-K partials stage A
__device__ float g_PB[32 * BATCH * HID];                // split-K partials stage B
__device__ volatile unsigned g_bar;                     // grid barrier counter

// ---------------- init ----------------
__global__ void init_kernel() {
    int i = blockIdx.x * blockDim.x + threadIdx.x;
    if (i == 0) g_bar = 0u;
    if (i < HID * BATCH) { g_hT[i] = 1e-9f; g_hb[i] = 1e-9f; }
}

// ---------------- convert: fp32 -> bf16 hi/lo for X and W rows ----------------
__global__ void convert_kernel(const float* __restrict__ x,
                               const float* __restrict__ Wfc,
                               const float* __restrict__ Wfc2) {
    int i = blockIdx.x * blockDim.x + threadIdx.x;
    const size_t NX = (size_t)MROWS * DIN;
    if ((size_t)i < NX) {
        float a = x[i];
        __nv_bfloat16 h = __float2bfloat16(a);
        g_Xh[i] = h;
        g_Xl[i] = __float2bfloat16(a - __bfloat162float(h));
    }
    if (i < N3 * DIN) {
        int n = i >> 10, k = i & 1023;
        float a = (n < 2048) ? Wfc[(size_t)n * 2048 + k]
                             : Wfc2[(size_t)(n - 2048) * 2048 + k];
        __nv_bfloat16 h = __float2bfloat16(a);
        g_Bh[i] = h;
        g_Bl[i] = __float2bfloat16(a - __bfloat162float(h));
    }
}

// ---------------- repack seq weights to k-major ----------------
__global__ void repack_kernel(const float* __restrict__ Wfc,
                              const float* __restrict__ Wfc2) {
    int i = blockIdx.x * blockDim.x + threadIdx.x;
    const int szA = HID * 2048;          // 2,097,152
    const int szB = HID * HID;           // 1,048,576
    if (i < szA) {
        int k = i >> 11, j = i & 2047;
        g_WtA[i] = Wfc[(size_t)j * 2048 + 1024 + k];
    } else if (i < szA + szB) {
        int j2 = i - szA; int k = j2 >> 10, j = j2 & 1023;
        g_WtB[j2] = Wfc2[(size_t)j * 2048 + 1024 + k];
    }
}

// ---------------- phase 1 (WMMA bf16 hi/lo split): P = X @ W^T ----------------
// 128x128 block tile, 8 warps in 2x4 grid, 64x32 warp tile.
// acc += Ah*Bh + Ah*Bl + Al*Bh  (AlBl dropped, ~2^-18 per-term relative)
#define LDT 40   // padded bf16 row pitch for 32-wide K tiles

__global__ void __launch_bounds__(256) gemm_p_wmma_kernel() {
    __shared__ __nv_bfloat16 Ah[128][LDT];
    __shared__ __nv_bfloat16 Al[128][LDT];
    __shared__ __nv_bfloat16 Bh[128][LDT];
    __shared__ __nv_bfloat16 Bl[128][LDT];

    const int tid = threadIdx.x, wid = tid >> 5;
    const int m0 = (blockIdx.x / 24) << 7;
    const int n0 = (blockIdx.x % 24) << 7;
    const int wm = (wid >> 2) << 6;   // warp row offset: 0 or 64
    const int wn = (wid & 3) << 5;    // warp col offset: 0,32,64,96

    wmma::fragment<wmma::accumulator, 16, 16, 16, float> acc[4][2];
#pragma unroll
    for (int i = 0; i < 4; i++)
#pragma unroll
        for (int j = 0; j < 2; j++) wmma::fill_fragment(acc[i][j], 0.0f);

    for (int k0 = 0; k0 < DIN; k0 += 32) {
        // load 4 tiles of 128x32 bf16 (each: 512 float4, 2 per thread)
#pragma unroll
        for (int i = tid; i < 512; i += 256) {
            int r = i >> 2, c = (i & 3) << 3;
            *(float4*)&Ah[r][c] = *(const float4*)(g_Xh + (size_t)(m0 + r) * DIN + k0 + c);
            *(float4*)&Al[r][c] = *(const float4*)(g_Xl + (size_t)(m0 + r) * DIN + k0 + c);
            *(float4*)&Bh[r][c] = *(const float4*)(g_Bh + (size_t)(n0 + r) * DIN + k0 + c);
            *(float4*)&Bl[r][c] = *(const float4*)(g_Bl + (size_t)(n0 + r) * DIN + k0 + c);
        }
        __syncthreads();
#pragma unroll
        for (int kk = 0; kk < 32; kk += 16) {
            wmma::fragment<wmma::matrix_a, 16, 16, 16, __nv_bfloat16, wmma::row_major> fah[4], fal[4];
            wmma::fragment<wmma::matrix_b, 16, 16, 16, __nv_bfloat16, wmma::col_major> fbh[2], fbl[2];
#pragma unroll
            for (int i = 0; i < 4; i++) {
                wmma::load_matrix_sync(fah[i], &Ah[wm + i * 16][kk], LDT);
                wmma::load_matrix_sync(fal[i], &Al[wm + i * 16][kk], LDT);
            }
#pragma unroll
            for (int j = 0; j < 2; j++) {
                wmma::load_matrix_sync(fbh[j], &Bh[wn + j * 16][kk], LDT);
                wmma::load_matrix_sync(fbl[j], &Bl[wn + j * 16][kk], LDT);
            }
#pragma unroll
            for (int i = 0; i < 4; i++)
#pragma unroll
                for (int j = 0; j < 2; j++) {
                    wmma::mma_sync(acc[i][j], fah[i], fbh[j], acc[i][j]);
                    wmma::mma_sync(acc[i][j], fah[i], fbl[j], acc[i][j]);
                    wmma::mma_sync(acc[i][j], fal[i], fbh[j], acc[i][j]);
                }
        }
        __syncthreads();
    }
#pragma unroll
    for (int i = 0; i < 4; i++)
#pragma unroll
        for (int j = 0; j < 2; j++)
            wmma::store_matrix_sync(
                g_P + (size_t)(m0 + wm + i * 16) * N3 + n0 + wn + j * 16,
                acc[i][j], N3, wmma::mem_row_major);
}

// ---------------- robust grid barrier (monotonic counter) ----------------
__device__ __forceinline__ void grid_bar(unsigned target) {
    __threadfence();
    __syncthreads();
    if (threadIdx.x == 0) {
        atomicAdd((unsigned*)&g_bar, 1u);
        while (g_bar < target) __nanosleep(64);
        __threadfence();
    }
    __syncthreads();
}

#define TEAM_BAR(h) asm volatile("bar.sync %0, 256;" :: "r"(1 + (h)) : "memory")

// ---------------- persistent sequential kernel (512 threads = 2 teams) ----------------
__global__ void __launch_bounds__(512, 1) seq_kernel(float* __restrict__ out) {
    __shared__ float As[2][16][64];
    __shared__ float Bs[2][16][128];
    __shared__ float rhs[2][32][65];
    const int tid = threadIdx.x, bid = blockIdx.x, nb = gridDim.x;
    const int h = tid >> 8, ttid = tid & 255;
    const int team = bid * 2 + h;
    const int gtid = bid * 512 + tid, nthr = nb * 512;
    const int tx4 = (ttid & 31) << 2;
    const int ty8 = (ttid >> 5) << 3;
    unsigned bar_t = 0;

    for (int t = 0; t < T_STEPS; t++) {
        const float* Pt = g_P + (size_t)t * (BATCH * N3);

        // ======== stage A: PA[kc] = hT[kc-slice] @ WtA  (16 kc x 16 ct = 256 units, 64x128 tiles)
        if (team < 256) {
            const int kc = team >> 4, ct = team & 15;
            const float* Ak = g_hT + kc * 64 * 64;
            const float* Bk = g_WtA + (size_t)(kc * 64) * 2048 + ct * 128;
            float* C = g_PA + (size_t)kc * (BATCH * 2048) + ct * 128;
            float acc[8][4];
#pragma unroll
            for (int i = 0; i < 8; i++)
#pragma unroll
                for (int j = 0; j < 4; j++) acc[i][j] = 0.f;

            for (int kb = 0; kb < 64; kb += 16) {
                {
                    int r = ttid >> 4, c4 = (ttid & 15) << 2;
                    *(float4*)&As[h][r][c4] = __ldcg((const float4*)(Ak + (kb + r) * 64 + c4));
                }
#pragma unroll
                for (int i = 0; i < 2; i++) {
                    int idx = (i << 8) | ttid;
                    int r = idx >> 5, c4 = (idx & 31) << 2;
                    *(float4*)&Bs[h][r][c4] =
                        *(const float4*)(Bk + (size_t)(kb + r) * 2048 + c4);
                }
                TEAM_BAR(h);
#pragma unroll
                for (int k = 0; k < 16; k++) {
                    float4 a0 = *(const float4*)&As[h][k][ty8];
                    float4 a1 = *(const float4*)&As[h][k][ty8 + 4];
                    float4 b0 = *(const float4*)&Bs[h][k][tx4];
                    float a[8] = {a0.x, a0.y, a0.z, a0.w, a1.x, a1.y, a1.z, a1.w};
                    float b[4] = {b0.x, b0.y, b0.z, b0.w};
#pragma unroll
                    for (int i = 0; i < 8; i++)
#pragma unroll
                        for (int j = 0; j < 4; j++)
                            acc[i][j] = fmaf(a[i], b[j], acc[i][j]);
                }
                TEAM_BAR(h);
            }
#pragma unroll
            for (int i = 0; i < 8; i++)
                *(float4*)(C + (size_t)(ty8 + i) * 2048 + tx4) =
                    make_float4(acc[i][0], acc[i][1], acc[i][2], acc[i][3]);
        }
        bar_t += nb; grid_bar(bar_t);

        // ======== stage B: fused r-reduce + (r*h) @ WtB  (32 kc x 8 ct = 256 units, 64x128 tiles)
        if (team < 256) {
            const int kc = team >> 3, ct = team & 7;

            for (int idx = ttid; idx < 32 * 64; idx += 256) {
                int kl = idx & 31, b = idx >> 5;
                int k = kc * 32 + kl;
                float s = Pt[b * N3 + 1024 + k];
#pragma unroll
                for (int c = 0; c < 16; c++)
                    s += __ldcg(&g_PA[c * (BATCH * 2048) + b * 2048 + 1024 + k]);
                float r = 1.0f / (1.0f + __expf(-s));
                rhs[h][kl][b] = r * __ldcg(&g_hb[(b << 10) + k]);
            }
            TEAM_BAR(h);

            const float* Bk = g_WtB + (size_t)(kc * 32) * 1024 + ct * 128;
            float* C = g_PB + (size_t)kc * (BATCH * 1024) + ct * 128;
            float acc[8][4];
#pragma unroll
            for (int i = 0; i < 8; i++)
#pragma unroll
                for (int j = 0; j < 4; j++) acc[i][j] = 0.f;

            for (int kb = 0; kb < 32; kb += 16) {
#pragma unroll
                for (int i = 0; i < 2; i++) {
                    int idx = (i << 8) | ttid;
                    int r = idx >> 5, c4 = (idx & 31) << 2;
                    *(float4*)&Bs[h][r][c4] =
                        *(const float4*)(Bk + (size_t)(kb + r) * 1024 + c4);
                }
                TEAM_BAR(h);
#pragma unroll
                for (int k = 0; k < 16; k++) {
                    const float* ar = &rhs[h][kb + k][0];
                    float4 b0 = *(const float4*)&Bs[h][k][tx4];
                    float b[4] = {b0.x, b0.y, b0.z, b0.w};
#pragma unroll
                    for (int i = 0; i < 8; i++) {
                        float a = ar[ty8 + i];
#pragma unroll
                        for (int j = 0; j < 4; j++)
                            acc[i][j] = fmaf(a, b[j], acc[i][j]);
                    }
                }
                TEAM_BAR(h);
            }
#pragma unroll
            for (int i = 0; i < 8; i++)
                *(float4*)(C + (size_t)(ty8 + i) * 1024 + tx4) =
                    make_float4(acc[i][0], acc[i][1], acc[i][2], acc[i][3]);
        }
        bar_t += nb; grid_bar(bar_t);

        // ======== stage C: z reduce + tanh(c) + blend + h update + output
        float* ot = out + (size_t)t * (BATCH * HID);
        for (int o = gtid; o < BATCH * HID; o += nthr) {
            int b = o >> 10, j = o & 1023;
            float sz = Pt[b * N3 + j];
#pragma unroll
            for (int c = 0; c < 16; c++)
                sz += __ldcg(&g_PA[c * (BATCH * 2048) + b * 2048 + j]);
            float z = 1.0f / (1.0f + __expf(-sz));

            float sc = Pt[b * N3 + 2048 + j];
#pragma unroll
            for (int c = 0; c < 32; c++)
                sc += __ldcg(&g_PB[c * (BATCH * 1024) + o]);
            float cv = tanhf(sc);

            float hcur = __ldcg(&g_hb[o]);
            float hn = fmaf(z, cv - hcur, hcur);   // (1-z)*h + z*c
            ot[o] = hn;
            g_hb[o] = hn;
            g_hT[(j << 6) + b] = hn;
        }
        bar_t += nb; grid_bar(bar_t);
    }
}

// ---------------- launch (5 graph nodes total) ----------------
extern "C" void kernel_launch(void* const* d_in, const int* in_sizes, int n_in,
                              void* d_out, int out_size) {
    const float* x    = (const float*)d_in[0];   // [512, 64, 1024]
    const float* Wfc  = (const float*)d_in[1];   // [2048, 2048]
    const float* Wfc2 = (const float*)d_in[2];   // [1024, 2048]
    // d_in[3] (w_hh), d_in[4] (bias): dead — delta_u never reaches the output
    float* out = (float*)d_out;                  // [512, 64, 1024]

    int sms = 148;
    cudaDeviceGetAttribute(&sms, cudaDevAttrMultiProcessorCount, 0);
    if (sms > 148) sms = 148;

    init_kernel<<<256, 256>>>();
    convert_kernel<<<(MROWS * DIN + 255) / 256, 256>>>(x, Wfc, Wfc2);
    repack_kernel<<<12288, 256>>>(Wfc, Wfc2);
    gemm_p_wmma_kernel<<<(MROWS / 128) * (N3 / 128), 256>>>();
    seq_kernel<<<sms, 512>>>(out);
}